// round 1
// baseline (speedup 1.0000x reference)
#include <cuda_runtime.h>
#include <cuda_bf16.h>
#include <math_constants.h>

// ---------------- problem constants ----------------
constexpr int B  = 8;
constexpr int S  = 1024;
constexpr int D  = 1024;
constexpr int H  = 16;
constexpr int DK = 64;
constexpr int F  = 4096;
constexpr int M  = B * S;        // 8192 rows
constexpr int N3 = 3 * D;        // 3072 (Q|K|V concat)

// ---------------- scratch (static device memory; no allocation) ----------------
__device__ float g_Wqkv[(size_t)D * N3];          // [D][3072] repacked weights
__device__ float g_bqkv[N3];
__device__ float g_QKV [(size_t)M * N3];          // [M][3072]  Q|K|V
__device__ float g_P   [(size_t)B * H * S * S];   // attention logits/probs (537 MB)
__device__ float g_CTX [(size_t)M * D];           // head-concat context
__device__ float g_Y   [(size_t)M * D];           // src + attn_out
__device__ float g_X   [(size_t)M * D];           // LN1 output
__device__ float g_Hf  [(size_t)M * F];           // FFN hidden
__device__ float g_Z   [(size_t)M * D];           // x + ffn

// ---------------- weight repack ----------------
// g_Wqkv[d][m*1024 + h*64 + k] = W{q,k,v}[h][d][k];  bias similarly.
__global__ __launch_bounds__(256) void prep_k(
    const float* __restrict__ Wq, const float* __restrict__ Wk, const float* __restrict__ Wv,
    const float* __restrict__ bq, const float* __restrict__ bk, const float* __restrict__ bv)
{
    int idx = blockIdx.x * blockDim.x + threadIdx.x;
    int total = H * D * DK;                       // 1,048,576 per matrix
    if (idx < total) {
        int h   = idx / (D * DK);
        int rem = idx - h * (D * DK);
        int d   = rem / DK;
        int k   = rem - d * DK;
        size_t dst = (size_t)d * N3 + h * DK + k;
        g_Wqkv[dst         ] = Wq[idx];
        g_Wqkv[dst + D     ] = Wk[idx];
        g_Wqkv[dst + 2 * D ] = Wv[idx];
    }
    if (idx < D) {
        g_bqkv[idx        ] = bq[idx];
        g_bqkv[idx + D    ] = bk[idx];
        g_bqkv[idx + 2 * D] = bv[idx];
    }
}

// ---------------- generic SGEMM: C[M,N] = A[M,K] @ B[K,N] (+bias)(+resid)(relu) ----------------
// 128x128 block tile, BK=16, 256 threads, 8x8 per-thread microtile.
// All dims must be multiples of (128,128,16) -- true for every call here.
__global__ __launch_bounds__(256) void sgemm_k(
    const float* __restrict__ A, const float* __restrict__ Bm, float* __restrict__ C,
    const float* __restrict__ bias, const float* __restrict__ resid,
    int Mm, int Nn, int Kk, int relu)
{
    constexpr int BM = 128, BN = 128, BK = 16;
    __shared__ float As[BK][BM];
    __shared__ float Bs[BK][BN];

    int tid  = threadIdx.x;
    int row0 = blockIdx.y * BM;
    int col0 = blockIdx.x * BN;
    int tx = tid & 15, ty = tid >> 4;            // 16x16 thread grid

    float acc[8][8];
    #pragma unroll
    for (int i = 0; i < 8; i++)
        #pragma unroll
        for (int j = 0; j < 8; j++) acc[i][j] = 0.f;

    for (int k0 = 0; k0 < Kk; k0 += BK) {
        // load A tile (128x16): 512 float4, 2 per thread, stored transposed
        #pragma unroll
        for (int i = 0; i < 2; i++) {
            int id = tid * 2 + i;                // 0..511
            int r  = id >> 2;                    // 0..127
            int c  = (id & 3) << 2;              // 0,4,8,12
            float4 v = *reinterpret_cast<const float4*>(A + (size_t)(row0 + r) * Kk + k0 + c);
            As[c + 0][r] = v.x; As[c + 1][r] = v.y; As[c + 2][r] = v.z; As[c + 3][r] = v.w;
        }
        // load B tile (16x128): 512 float4, 2 per thread
        #pragma unroll
        for (int i = 0; i < 2; i++) {
            int id = tid * 2 + i;
            int r  = id >> 5;                    // 0..15
            int c  = (id & 31) << 2;             // 0..124
            *reinterpret_cast<float4*>(&Bs[r][c]) =
                *reinterpret_cast<const float4*>(Bm + (size_t)(k0 + r) * Nn + col0 + c);
        }
        __syncthreads();

        #pragma unroll
        for (int kk = 0; kk < BK; kk++) {
            float ra[8], rb[8];
            #pragma unroll
            for (int i = 0; i < 8; i++) ra[i] = As[kk][ty * 8 + i];
            #pragma unroll
            for (int j = 0; j < 8; j++) rb[j] = Bs[kk][tx * 8 + j];
            #pragma unroll
            for (int i = 0; i < 8; i++)
                #pragma unroll
                for (int j = 0; j < 8; j++)
                    acc[i][j] = fmaf(ra[i], rb[j], acc[i][j]);
        }
        __syncthreads();
    }

    // epilogue
    #pragma unroll
    for (int i = 0; i < 8; i++) {
        int r = row0 + ty * 8 + i;
        #pragma unroll
        for (int j = 0; j < 8; j++) {
            int c = col0 + tx * 8 + j;
            float v = acc[i][j];
            if (bias)  v += bias[c];
            if (resid) v += resid[(size_t)r * Nn + c];
            if (relu)  v = fmaxf(v, 0.f);
            C[(size_t)r * Nn + c] = v;
        }
    }
}

// ---------------- attention logits: P[bh][s][t] = (q.k)/8 + mask*(-1e9) ----------------
// grid (S/64, S/64, B*H), 64x64 tile, K=64 fully resident in smem.
__global__ __launch_bounds__(256) void attn_logits_k(
    const float* __restrict__ QKV, const float* __restrict__ mask, float* __restrict__ P)
{
    int bh = blockIdx.z;
    int b  = bh >> 4, h = bh & 15;
    int s0 = blockIdx.y * 64, t0 = blockIdx.x * 64;

    const float* Qb = QKV + (size_t)b * S * N3 + h * DK;
    const float* Kb = Qb + D;

    __shared__ float Qs[64][64];   // [k][s]
    __shared__ float Ks[64][64];   // [k][t]

    int tid = threadIdx.x;
    #pragma unroll
    for (int i = 0; i < 4; i++) {
        int id = tid * 4 + i;      // 0..1023
        int r  = id >> 4;          // 0..63
        int c  = (id & 15) << 2;   // 0..60
        float4 q  = *reinterpret_cast<const float4*>(Qb + (size_t)(s0 + r) * N3 + c);
        Qs[c + 0][r] = q.x;  Qs[c + 1][r] = q.y;  Qs[c + 2][r] = q.z;  Qs[c + 3][r] = q.w;
        float4 kv = *reinterpret_cast<const float4*>(Kb + (size_t)(t0 + r) * N3 + c);
        Ks[c + 0][r] = kv.x; Ks[c + 1][r] = kv.y; Ks[c + 2][r] = kv.z; Ks[c + 3][r] = kv.w;
    }
    __syncthreads();

    int tx = tid & 15, ty = tid >> 4;
    float acc[4][4] = {};
    #pragma unroll
    for (int k = 0; k < 64; k++) {
        float rq[4], rk[4];
        #pragma unroll
        for (int i = 0; i < 4; i++) rq[i] = Qs[k][ty * 4 + i];
        #pragma unroll
        for (int j = 0; j < 4; j++) rk[j] = Ks[k][tx * 4 + j];
        #pragma unroll
        for (int i = 0; i < 4; i++)
            #pragma unroll
            for (int j = 0; j < 4; j++)
                acc[i][j] = fmaf(rq[i], rk[j], acc[i][j]);
    }

    float* Pb = P + (size_t)bh * S * S;
    #pragma unroll
    for (int i = 0; i < 4; i++) {
        int s = s0 + ty * 4 + i;
        #pragma unroll
        for (int j = 0; j < 4; j++) {
            int t = t0 + tx * 4 + j;
            Pb[(size_t)s * S + t] = acc[i][j] * 0.125f + mask[s * S + t] * (-1e9f);
        }
    }
}

// ---------------- row softmax over 1024 columns ----------------
__global__ __launch_bounds__(256) void softmax_k(float* __restrict__ P)
{
    __shared__ float sh[8];
    __shared__ float shb;
    size_t row = blockIdx.x;
    float* p = P + row * (size_t)S;
    int tid = threadIdx.x, lane = tid & 31, wp = tid >> 5;

    float4 v = *reinterpret_cast<float4*>(p + tid * 4);
    float m = fmaxf(fmaxf(v.x, v.y), fmaxf(v.z, v.w));
    #pragma unroll
    for (int o = 16; o; o >>= 1) m = fmaxf(m, __shfl_down_sync(~0u, m, o));
    if (!lane) sh[wp] = m;
    __syncthreads();
    if (tid < 32) {
        m = (tid < 8) ? sh[tid] : -CUDART_INF_F;
        #pragma unroll
        for (int o = 4; o; o >>= 1) m = fmaxf(m, __shfl_down_sync(~0u, m, o));
        if (!tid) shb = m;
    }
    __syncthreads();
    m = shb;

    v.x = __expf(v.x - m); v.y = __expf(v.y - m);
    v.z = __expf(v.z - m); v.w = __expf(v.w - m);
    float s = v.x + v.y + v.z + v.w;
    __syncthreads();                              // before reusing sh
    #pragma unroll
    for (int o = 16; o; o >>= 1) s += __shfl_down_sync(~0u, s, o);
    if (!lane) sh[wp] = s;
    __syncthreads();
    if (tid < 32) {
        s = (tid < 8) ? sh[tid] : 0.f;
        #pragma unroll
        for (int o = 4; o; o >>= 1) s += __shfl_down_sync(~0u, s, o);
        if (!tid) shb = s;
    }
    __syncthreads();
    float inv = __frcp_rn(shb);
    v.x *= inv; v.y *= inv; v.z *= inv; v.w *= inv;
    *reinterpret_cast<float4*>(p + tid * 4) = v;
}

// ---------------- context: CTX[b][s][h*64+v] = sum_t P[bh][s][t] * V[b][t][h*64+v] ----------------
// grid (1, S/64, B*H). BM=64 (s), BN=64 (v, full), BK=16 (t).
__global__ __launch_bounds__(256) void attn_ctx_k(
    const float* __restrict__ P, const float* __restrict__ QKV, float* __restrict__ CTX)
{
    int bh = blockIdx.z;
    int b  = bh >> 4, h = bh & 15;
    int s0 = blockIdx.y * 64;

    const float* Pb = P + (size_t)bh * S * S;
    const float* Vb = QKV + (size_t)b * S * N3 + 2 * D + h * DK;

    __shared__ float Ps[16][64];   // [t][s]
    __shared__ float Vs[16][64];   // [t][v]

    int tid = threadIdx.x, tx = tid & 15, ty = tid >> 4;
    float acc[4][4] = {};

    for (int t0 = 0; t0 < S; t0 += 16) {
        {   // P tile 64(s) x 16(t): 256 float4, 1/thread, store transposed
            int r = tid >> 2, c = (tid & 3) << 2;
            float4 v = *reinterpret_cast<const float4*>(Pb + (size_t)(s0 + r) * S + t0 + c);
            Ps[c + 0][r] = v.x; Ps[c + 1][r] = v.y; Ps[c + 2][r] = v.z; Ps[c + 3][r] = v.w;
        }
        {   // V tile 16(t) x 64(v): 256 float4, 1/thread
            int r = tid >> 4, c = (tid & 15) << 2;
            *reinterpret_cast<float4*>(&Vs[r][c]) =
                *reinterpret_cast<const float4*>(Vb + (size_t)(t0 + r) * N3 + c);
        }
        __syncthreads();
        #pragma unroll
        for (int kk = 0; kk < 16; kk++) {
            float ra[4], rb[4];
            #pragma unroll
            for (int i = 0; i < 4; i++) ra[i] = Ps[kk][ty * 4 + i];
            #pragma unroll
            for (int j = 0; j < 4; j++) rb[j] = Vs[kk][tx * 4 + j];
            #pragma unroll
            for (int i = 0; i < 4; i++)
                #pragma unroll
                for (int j = 0; j < 4; j++)
                    acc[i][j] = fmaf(ra[i], rb[j], acc[i][j]);
        }
        __syncthreads();
    }

    #pragma unroll
    for (int i = 0; i < 4; i++) {
        int s = s0 + ty * 4 + i;
        #pragma unroll
        for (int j = 0; j < 4; j++) {
            CTX[(size_t)(b * S + s) * D + h * DK + tx * 4 + j] = acc[i][j];
        }
    }
}

// ---------------- LayerNorm over last dim (1024) ----------------
__global__ __launch_bounds__(256) void layernorm_k(
    const float* __restrict__ in, const float* __restrict__ w,
    const float* __restrict__ bb, float* __restrict__ out)
{
    __shared__ float sh1[8], sh2[8], shb[2];
    size_t row = blockIdx.x;
    const float* x = in + row * D;
    int tid = threadIdx.x, lane = tid & 31, wp = tid >> 5;

    float4 v = *reinterpret_cast<const float4*>(x + tid * 4);
    float s = v.x + v.y + v.z + v.w;
    float q = v.x * v.x + v.y * v.y + v.z * v.z + v.w * v.w;
    #pragma unroll
    for (int o = 16; o; o >>= 1) { s += __shfl_down_sync(~0u, s, o); q += __shfl_down_sync(~0u, q, o); }
    if (!lane) { sh1[wp] = s; sh2[wp] = q; }
    __syncthreads();
    if (tid < 32) {
        s = (tid < 8) ? sh1[tid] : 0.f;
        q = (tid < 8) ? sh2[tid] : 0.f;
        #pragma unroll
        for (int o = 4; o; o >>= 1) { s += __shfl_down_sync(~0u, s, o); q += __shfl_down_sync(~0u, q, o); }
        if (!tid) {
            float mu = s * (1.f / D);
            shb[0] = mu;
            shb[1] = rsqrtf(q * (1.f / D) - mu * mu + 1e-5f);
        }
    }
    __syncthreads();
    float mu = shb[0], rs = shb[1];
    float4 wv = *reinterpret_cast<const float4*>(w  + tid * 4);
    float4 bv = *reinterpret_cast<const float4*>(bb + tid * 4);
    float4 o4;
    o4.x = (v.x - mu) * rs * wv.x + bv.x;
    o4.y = (v.y - mu) * rs * wv.y + bv.y;
    o4.z = (v.z - mu) * rs * wv.z + bv.z;
    o4.w = (v.w - mu) * rs * wv.w + bv.w;
    *reinterpret_cast<float4*>(out + row * D + tid * 4) = o4;
}

// ---------------- launch ----------------
extern "C" void kernel_launch(void* const* d_in, const int* in_sizes, int n_in,
                              void* d_out, int out_size)
{
    const float* src  = (const float*)d_in[0];
    const float* mask = (const float*)d_in[1];
    const float* Wq   = (const float*)d_in[2];
    const float* bq   = (const float*)d_in[3];
    const float* Wk   = (const float*)d_in[4];
    const float* bk   = (const float*)d_in[5];
    const float* Wv   = (const float*)d_in[6];
    const float* bv   = (const float*)d_in[7];
    const float* Wo   = (const float*)d_in[8];
    const float* bo   = (const float*)d_in[9];
    const float* ln1w = (const float*)d_in[10];
    const float* ln1b = (const float*)d_in[11];
    const float* W1   = (const float*)d_in[12];
    const float* b1   = (const float*)d_in[13];
    const float* W2   = (const float*)d_in[14];
    const float* b2   = (const float*)d_in[15];
    const float* ln2w = (const float*)d_in[16];
    const float* ln2b = (const float*)d_in[17];
    float* out = (float*)d_out;

    float *pWqkv, *pbqkv, *pQKV, *pP, *pCTX, *pY, *pX, *pHf, *pZ;
    cudaGetSymbolAddress((void**)&pWqkv, g_Wqkv);
    cudaGetSymbolAddress((void**)&pbqkv, g_bqkv);
    cudaGetSymbolAddress((void**)&pQKV,  g_QKV);
    cudaGetSymbolAddress((void**)&pP,    g_P);
    cudaGetSymbolAddress((void**)&pCTX,  g_CTX);
    cudaGetSymbolAddress((void**)&pY,    g_Y);
    cudaGetSymbolAddress((void**)&pX,    g_X);
    cudaGetSymbolAddress((void**)&pHf,   g_Hf);
    cudaGetSymbolAddress((void**)&pZ,    g_Z);

    // 1) repack QKV weights
    prep_k<<<(H * D * DK + 255) / 256, 256>>>(Wq, Wk, Wv, bq, bk, bv);

    // 2) QKV = src @ Wqkv + bqkv   [8192 x 3072]
    sgemm_k<<<dim3(N3 / 128, M / 128), 256>>>(src, pWqkv, pQKV, pbqkv, nullptr, M, N3, D, 0);

    // 3) logits (scaled + masked)
    attn_logits_k<<<dim3(S / 64, S / 64, B * H), 256>>>(pQKV, mask, pP);

    // 4) softmax
    softmax_k<<<B * H * S, 256>>>(pP);

    // 5) context (head-concat layout)
    attn_ctx_k<<<dim3(1, S / 64, B * H), 256>>>(pP, pQKV, pCTX);

    // 6) Y = src + CTX @ Wo + bo
    sgemm_k<<<dim3(D / 128, M / 128), 256>>>(pCTX, Wo, pY, bo, src, M, D, D, 0);

    // 7) X = LN1(Y)
    layernorm_k<<<M, 256>>>(pY, ln1w, ln1b, pX);

    // 8) Hf = relu(X @ W1 + b1)
    sgemm_k<<<dim3(F / 128, M / 128), 256>>>(pX, W1, pHf, b1, nullptr, M, F, D, 1);

    // 9) Z = X + Hf @ W2 + b2
    sgemm_k<<<dim3(D / 128, M / 128), 256>>>(pHf, W2, pZ, b2, pX, M, D, F, 0);

    // 10) out = LN2(Z)
    layernorm_k<<<M, 256>>>(pZ, ln2w, ln2b, out);
}

// round 3
// speedup vs baseline: 1.8208x; 1.8208x over previous
#include <cuda_runtime.h>
#include <cuda_bf16.h>
#include <math_constants.h>
#include <cstdint>

// ---------------- problem constants ----------------
constexpr int B  = 8;
constexpr int S  = 1024;
constexpr int D  = 1024;
constexpr int H  = 16;
constexpr int DK = 64;
constexpr int F  = 4096;
constexpr int M  = B * S;        // 8192 rows
constexpr int N3 = 3 * D;        // 3072 (Q|K|V concat)

// ---------------- scratch (static device memory; no allocation) ----------------
__device__ __align__(128) float g_Wqkv[(size_t)D * N3];
__device__ __align__(128) float g_bqkv[N3];
__device__ __align__(128) float g_QKV [(size_t)M * N3];
__device__ __align__(128) float g_P   [(size_t)B * H * S * S];
__device__ __align__(128) float g_CTX [(size_t)M * D];
__device__ __align__(128) float g_Y   [(size_t)M * D];
__device__ __align__(128) float g_X   [(size_t)M * D];
__device__ __align__(128) float g_Hf  [(size_t)M * F];
__device__ __align__(128) float g_Z   [(size_t)M * D];

// packed bf16 hi/lo weight planes, K-major: plane[n*K + k]
__device__ __align__(128) __nv_bfloat16 g_qkv_h[(size_t)N3 * D];
__device__ __align__(128) __nv_bfloat16 g_qkv_l[(size_t)N3 * D];
__device__ __align__(128) __nv_bfloat16 g_wo_h [(size_t)D * D];
__device__ __align__(128) __nv_bfloat16 g_wo_l [(size_t)D * D];
__device__ __align__(128) __nv_bfloat16 g_w1_h [(size_t)F * D];
__device__ __align__(128) __nv_bfloat16 g_w1_l [(size_t)F * D];
__device__ __align__(128) __nv_bfloat16 g_w2_h [(size_t)D * F];
__device__ __align__(128) __nv_bfloat16 g_w2_l [(size_t)D * F];

// ---------------- PTX helpers (sm_80-era only; no tcgen05 on plain sm_103 target) ----------------
__device__ __forceinline__ uint32_t smem_u32(const void* p) {
    uint32_t a;
    asm("{ .reg .u64 t; cvta.to.shared.u64 t, %1; cvt.u32.u64 %0, t; }" : "=r"(a) : "l"(p));
    return a;
}
__device__ __forceinline__ void sts64(uint32_t a, uint32_t x, uint32_t y) {
    asm volatile("st.shared.v2.b32 [%0], {%1, %2};" :: "r"(a), "r"(x), "r"(y));
}
#define CP16(dst, src) \
    asm volatile("cp.async.cg.shared.global [%0], [%1], 16;" :: "r"(dst), "l"(src) : "memory")
#define CP_COMMIT() asm volatile("cp.async.commit_group;" ::: "memory")
#define CP_WAIT0()  asm volatile("cp.async.wait_group 0;" ::: "memory")

#define LDSM4(r, addr) \
    asm volatile("ldmatrix.sync.aligned.m8n8.x4.shared.b16 {%0, %1, %2, %3}, [%4];" \
        : "=r"((r)[0]), "=r"((r)[1]), "=r"((r)[2]), "=r"((r)[3]) : "r"(addr))

#define MMA16816(d, a, b) \
    asm volatile("mma.sync.aligned.m16n8k16.row.col.f32.bf16.bf16.f32 " \
        "{%0, %1, %2, %3}, {%4, %5, %6, %7}, {%8, %9}, {%0, %1, %2, %3};" \
        : "+f"((d)[0]), "+f"((d)[1]), "+f"((d)[2]), "+f"((d)[3]) \
        : "r"((a)[0]), "r"((a)[1]), "r"((a)[2]), "r"((a)[3]), "r"((b)[0]), "r"((b)[1]))

// ---------------- weight repack (fp32 QKV concat) ----------------
__global__ __launch_bounds__(256) void prep_k(
    const float* __restrict__ Wq, const float* __restrict__ Wk, const float* __restrict__ Wv,
    const float* __restrict__ bq, const float* __restrict__ bk, const float* __restrict__ bv)
{
    int idx = blockIdx.x * blockDim.x + threadIdx.x;
    int total = H * D * DK;
    if (idx < total) {
        int h   = idx / (D * DK);
        int rem = idx - h * (D * DK);
        int d   = rem / DK;
        int k   = rem - d * DK;
        size_t dst = (size_t)d * N3 + h * DK + k;
        g_Wqkv[dst        ] = Wq[idx];
        g_Wqkv[dst + D    ] = Wk[idx];
        g_Wqkv[dst + 2 * D] = Wv[idx];
    }
    if (idx < D) {
        g_bqkv[idx        ] = bq[idx];
        g_bqkv[idx + D    ] = bk[idx];
        g_bqkv[idx + 2 * D] = bv[idx];
    }
}

// ---------------- transpose + bf16 hi/lo split: W[K][N] -> planes [N][K] ----------------
__global__ __launch_bounds__(256) void convW_k(
    const float* __restrict__ W, __nv_bfloat16* __restrict__ oh,
    __nv_bfloat16* __restrict__ ol, int Kk, int Nn)
{
    __shared__ float t[32][33];
    int n0 = blockIdx.x * 32, k0 = blockIdx.y * 32;
    int tx = threadIdx.x & 31, ty = threadIdx.x >> 5;   // 32 x 8
    #pragma unroll
    for (int i = 0; i < 4; i++)
        t[ty + i * 8][tx] = W[(size_t)(k0 + ty + i * 8) * Nn + n0 + tx];
    __syncthreads();
    #pragma unroll
    for (int i = 0; i < 4; i++) {
        int n = n0 + ty + i * 8;
        float v = t[tx][ty + i * 8];
        __nv_bfloat16 hv = __float2bfloat16(v);
        oh[(size_t)n * Kk + k0 + tx] = hv;
        ol[(size_t)n * Kk + k0 + tx] = __float2bfloat16(v - __bfloat162float(hv));
    }
}

// ---------------- HMMA GEMM: C[M,N] = A[M,K](fp32) @ Bplanes[N,K](bf16 hi/lo)^T ----------------
// 128x128x32 CTA tile, 8 warps (2M x 4N), 64x32 warp tile, m16n8k16 bf16 mma,
// 3-term hi/lo split, 2-stage smem ring. Padded rows (40 halves) => conflict-free ldmatrix.
constexpr int GLDS  = 40;                 // halves per smem row (32 data + 8 pad)
constexpr int GPL   = 128 * GLDS * 2;     // plane bytes  = 10240
constexpr int GSTG  = 4 * GPL;            // stage bytes  = 40960 (Ah|Al|Bh|Bl)
constexpr int GEMM_DSMEM = 2 * GSTG;      // 81920

__global__ __launch_bounds__(256, 1) void gemm_mma(
    const float* __restrict__ A, const __nv_bfloat16* __restrict__ Bhp,
    const __nv_bfloat16* __restrict__ Blp, float* __restrict__ C,
    const float* __restrict__ bias, const float* __restrict__ resid,
    int Nn, int Kk, int relu)
{
    extern __shared__ char smraw[];
    const uint32_t sbase = smem_u32(smraw);
    const int tid  = threadIdx.x;
    const int lane = tid & 31;
    const int wid  = tid >> 5;
    const int wm   = wid & 1;            // 2 warps in M
    const int wn   = wid >> 1;           // 4 warps in N
    const int m0 = blockIdx.y * 128;
    const int n0 = blockIdx.x * 128;
    const int nk = Kk >> 5;

    float acc[4][4][4];
    #pragma unroll
    for (int i = 0; i < 4; i++)
        #pragma unroll
        for (int j = 0; j < 4; j++)
            #pragma unroll
            for (int q = 0; q < 4; q++) acc[i][j][q] = 0.f;

    float4 aReg[4];

    // ---- stage-load helpers (expanded inline via lambdas) ----
    auto ldgA = [&](int ci) {
        #pragma unroll
        for (int p = 0; p < 4; p++) {
            int f = tid + (p << 8);
            int r = f >> 3, sg = f & 7;
            aReg[p] = *reinterpret_cast<const float4*>(
                A + (size_t)(m0 + r) * Kk + (ci << 5) + sg * 4);
        }
    };
    auto stsA = [&](int stage) {
        const uint32_t ab = sbase + stage * GSTG;
        #pragma unroll
        for (int p = 0; p < 4; p++) {
            int f = tid + (p << 8);
            int r = f >> 3, sg = f & 7;
            float4 v = aReg[p];
            __nv_bfloat16 hx = __float2bfloat16(v.x), hy = __float2bfloat16(v.y);
            __nv_bfloat16 hz = __float2bfloat16(v.z), hw = __float2bfloat16(v.w);
            __nv_bfloat162 h01; h01.x = hx; h01.y = hy;
            __nv_bfloat162 h23; h23.x = hz; h23.y = hw;
            __nv_bfloat162 l01, l23;
            l01.x = __float2bfloat16(v.x - __bfloat162float(hx));
            l01.y = __float2bfloat16(v.y - __bfloat162float(hy));
            l23.x = __float2bfloat16(v.z - __bfloat162float(hz));
            l23.y = __float2bfloat16(v.w - __bfloat162float(hw));
            uint32_t off = (uint32_t)(r * (GLDS * 2) + sg * 8);
            sts64(ab + off,       *reinterpret_cast<uint32_t*>(&h01), *reinterpret_cast<uint32_t*>(&h23));
            sts64(ab + GPL + off, *reinterpret_cast<uint32_t*>(&l01), *reinterpret_cast<uint32_t*>(&l23));
        }
    };
    auto cpB = [&](int ci, int stage) {
        const uint32_t bb = sbase + stage * GSTG + 2 * GPL;
        #pragma unroll
        for (int p = 0; p < 2; p++) {
            int f = tid + (p << 8);                  // 0..511
            int r = f >> 2, c = f & 3;
            uint32_t dst = bb + (uint32_t)(r * (GLDS * 2) + c * 16);
            const __nv_bfloat16* sh = Bhp + (size_t)(n0 + r) * Kk + (ci << 5) + c * 8;
            const __nv_bfloat16* sl = Blp + (size_t)(n0 + r) * Kk + (ci << 5) + c * 8;
            CP16(dst,       sh);
            CP16(dst + GPL, sl);
        }
        CP_COMMIT();
    };
    auto compute = [&](int stage) {
        const uint32_t ab = sbase + stage * GSTG;
        const uint32_t bb = ab + 2 * GPL;
        #pragma unroll
        for (int h = 0; h < 2; h++) {                        // two k16 halves of BK=32
            uint32_t Ahf[4][4], Alf[4][4], Bhf[4][2], Blf[4][2];
            #pragma unroll
            for (int i = 0; i < 4; i++) {
                int r = wm * 64 + i * 16 + (lane & 15);
                uint32_t ad = ab + (uint32_t)(r * (GLDS * 2) + h * 32 + (lane >> 4) * 16);
                LDSM4(Ahf[i], ad);
                LDSM4(Alf[i], ad + GPL);
            }
            #pragma unroll
            for (int jj = 0; jj < 2; jj++) {
                int nb = wn * 32 + jj * 16;
                int l8 = lane & 7, mt = lane >> 3;
                int nr = nb + (mt >> 1) * 8 + l8;
                uint32_t bd = bb + (uint32_t)(nr * (GLDS * 2) + h * 32 + (mt & 1) * 16);
                uint32_t q[4];
                LDSM4(q, bd);
                Bhf[jj * 2][0] = q[0]; Bhf[jj * 2][1] = q[1];
                Bhf[jj * 2 + 1][0] = q[2]; Bhf[jj * 2 + 1][1] = q[3];
                LDSM4(q, bd + GPL);
                Blf[jj * 2][0] = q[0]; Blf[jj * 2][1] = q[1];
                Blf[jj * 2 + 1][0] = q[2]; Blf[jj * 2 + 1][1] = q[3];
            }
            #pragma unroll
            for (int i = 0; i < 4; i++)
                #pragma unroll
                for (int j = 0; j < 4; j++) {
                    MMA16816(acc[i][j], Ahf[i], Bhf[j]);
                    MMA16816(acc[i][j], Alf[i], Bhf[j]);
                    MMA16816(acc[i][j], Ahf[i], Blf[j]);
                }
        }
    };

    // ---- prologue ----
    ldgA(0);
    cpB(0, 0);
    stsA(0);
    CP_WAIT0();
    __syncthreads();

    // ---- mainloop ----
    for (int i = 0; i < nk; i++) {
        const int st = i & 1;
        if (i + 1 < nk) { ldgA(i + 1); cpB(i + 1, st ^ 1); }
        compute(st);
        if (i + 1 < nk) stsA(st ^ 1);
        CP_WAIT0();
        __syncthreads();
    }

    // ---- epilogue: fragment layout m16n8 -> rows lane>>2 (+8), cols (lane&3)*2 ----
    #pragma unroll
    for (int i = 0; i < 4; i++) {
        int r = m0 + wm * 64 + i * 16 + (lane >> 2);
        #pragma unroll
        for (int j = 0; j < 4; j++) {
            int c = n0 + wn * 32 + j * 8 + (lane & 3) * 2;
            float2 v0 = { acc[i][j][0], acc[i][j][1] };
            float2 v1 = { acc[i][j][2], acc[i][j][3] };
            float2 bv = *reinterpret_cast<const float2*>(bias + c);
            v0.x += bv.x; v0.y += bv.y;
            v1.x += bv.x; v1.y += bv.y;
            if (resid) {
                float2 r0 = *reinterpret_cast<const float2*>(resid + (size_t)r * Nn + c);
                float2 r1 = *reinterpret_cast<const float2*>(resid + (size_t)(r + 8) * Nn + c);
                v0.x += r0.x; v0.y += r0.y;
                v1.x += r1.x; v1.y += r1.y;
            }
            if (relu) {
                v0.x = fmaxf(v0.x, 0.f); v0.y = fmaxf(v0.y, 0.f);
                v1.x = fmaxf(v1.x, 0.f); v1.y = fmaxf(v1.y, 0.f);
            }
            *reinterpret_cast<float2*>(C + (size_t)r * Nn + c) = v0;
            *reinterpret_cast<float2*>(C + (size_t)(r + 8) * Nn + c) = v1;
        }
    }
}

// ---------------- attention logits ----------------
__global__ __launch_bounds__(256) void attn_logits_k(
    const float* __restrict__ QKV, const float* __restrict__ mask, float* __restrict__ P)
{
    int bh = blockIdx.z;
    int b  = bh >> 4, h = bh & 15;
    int s0 = blockIdx.y * 64, t0 = blockIdx.x * 64;

    const float* Qb = QKV + (size_t)b * S * N3 + h * DK;
    const float* Kb = Qb + D;

    __shared__ float Qs[64][64];
    __shared__ float Ks[64][64];

    int tid = threadIdx.x;
    #pragma unroll
    for (int i = 0; i < 4; i++) {
        int id = tid * 4 + i;
        int r  = id >> 4;
        int c  = (id & 15) << 2;
        float4 q  = *reinterpret_cast<const float4*>(Qb + (size_t)(s0 + r) * N3 + c);
        Qs[c + 0][r] = q.x;  Qs[c + 1][r] = q.y;  Qs[c + 2][r] = q.z;  Qs[c + 3][r] = q.w;
        float4 kv = *reinterpret_cast<const float4*>(Kb + (size_t)(t0 + r) * N3 + c);
        Ks[c + 0][r] = kv.x; Ks[c + 1][r] = kv.y; Ks[c + 2][r] = kv.z; Ks[c + 3][r] = kv.w;
    }
    __syncthreads();

    int tx = tid & 15, ty = tid >> 4;
    float acc[4][4] = {};
    #pragma unroll
    for (int k = 0; k < 64; k++) {
        float rq[4], rk[4];
        #pragma unroll
        for (int i = 0; i < 4; i++) rq[i] = Qs[k][ty * 4 + i];
        #pragma unroll
        for (int j = 0; j < 4; j++) rk[j] = Ks[k][tx * 4 + j];
        #pragma unroll
        for (int i = 0; i < 4; i++)
            #pragma unroll
            for (int j = 0; j < 4; j++)
                acc[i][j] = fmaf(rq[i], rk[j], acc[i][j]);
    }

    float* Pb = P + (size_t)bh * S * S;
    #pragma unroll
    for (int i = 0; i < 4; i++) {
        int s = s0 + ty * 4 + i;
        #pragma unroll
        for (int j = 0; j < 4; j++) {
            int t = t0 + tx * 4 + j;
            Pb[(size_t)s * S + t] = acc[i][j] * 0.125f + mask[s * S + t] * (-1e9f);
        }
    }
}

// ---------------- row softmax over 1024 columns ----------------
__global__ __launch_bounds__(256) void softmax_k(float* __restrict__ P)
{
    __shared__ float sh[8];
    __shared__ float shb;
    size_t row = blockIdx.x;
    float* p = P + row * (size_t)S;
    int tid = threadIdx.x, lane = tid & 31, wp = tid >> 5;

    float4 v = *reinterpret_cast<float4*>(p + tid * 4);
    float m = fmaxf(fmaxf(v.x, v.y), fmaxf(v.z, v.w));
    #pragma unroll
    for (int o = 16; o; o >>= 1) m = fmaxf(m, __shfl_down_sync(~0u, m, o));
    if (!lane) sh[wp] = m;
    __syncthreads();
    if (tid < 32) {
        m = (tid < 8) ? sh[tid] : -CUDART_INF_F;
        #pragma unroll
        for (int o = 4; o; o >>= 1) m = fmaxf(m, __shfl_down_sync(~0u, m, o));
        if (!tid) shb = m;
    }
    __syncthreads();
    m = shb;

    v.x = __expf(v.x - m); v.y = __expf(v.y - m);
    v.z = __expf(v.z - m); v.w = __expf(v.w - m);
    float s = v.x + v.y + v.z + v.w;
    __syncthreads();
    #pragma unroll
    for (int o = 16; o; o >>= 1) s += __shfl_down_sync(~0u, s, o);
    if (!lane) sh[wp] = s;
    __syncthreads();
    if (tid < 32) {
        s = (tid < 8) ? sh[tid] : 0.f;
        #pragma unroll
        for (int o = 4; o; o >>= 1) s += __shfl_down_sync(~0u, s, o);
        if (!tid) shb = s;
    }
    __syncthreads();
    float inv = __frcp_rn(shb);
    v.x *= inv; v.y *= inv; v.z *= inv; v.w *= inv;
    *reinterpret_cast<float4*>(p + tid * 4) = v;
}

// ---------------- context ----------------
__global__ __launch_bounds__(256) void attn_ctx_k(
    const float* __restrict__ P, const float* __restrict__ QKV, float* __restrict__ CTX)
{
    int bh = blockIdx.z;
    int b  = bh >> 4, h = bh & 15;
    int s0 = blockIdx.y * 64;

    const float* Pb = P + (size_t)bh * S * S;
    const float* Vb = QKV + (size_t)b * S * N3 + 2 * D + h * DK;

    __shared__ float Ps[16][64];
    __shared__ float Vs[16][64];

    int tid = threadIdx.x, tx = tid & 15, ty = tid >> 4;
    float acc[4][4] = {};

    for (int t0 = 0; t0 < S; t0 += 16) {
        {
            int r = tid >> 2, c = (tid & 3) << 2;
            float4 v = *reinterpret_cast<const float4*>(Pb + (size_t)(s0 + r) * S + t0 + c);
            Ps[c + 0][r] = v.x; Ps[c + 1][r] = v.y; Ps[c + 2][r] = v.z; Ps[c + 3][r] = v.w;
        }
        {
            int r = tid >> 4, c = (tid & 15) << 2;
            *reinterpret_cast<float4*>(&Vs[r][c]) =
                *reinterpret_cast<const float4*>(Vb + (size_t)(t0 + r) * N3 + c);
        }
        __syncthreads();
        #pragma unroll
        for (int kk = 0; kk < 16; kk++) {
            float ra[4], rb[4];
            #pragma unroll
            for (int i = 0; i < 4; i++) ra[i] = Ps[kk][ty * 4 + i];
            #pragma unroll
            for (int j = 0; j < 4; j++) rb[j] = Vs[kk][tx * 4 + j];
            #pragma unroll
            for (int i = 0; i < 4; i++)
                #pragma unroll
                for (int j = 0; j < 4; j++)
                    acc[i][j] = fmaf(ra[i], rb[j], acc[i][j]);
        }
        __syncthreads();
    }

    #pragma unroll
    for (int i = 0; i < 4; i++) {
        int s = s0 + ty * 4 + i;
        #pragma unroll
        for (int j = 0; j < 4; j++) {
            CTX[(size_t)(b * S + s) * D + h * DK + tx * 4 + j] = acc[i][j];
        }
    }
}

// ---------------- LayerNorm over last dim (1024) ----------------
__global__ __launch_bounds__(256) void layernorm_k(
    const float* __restrict__ in, const float* __restrict__ w,
    const float* __restrict__ bb, float* __restrict__ out)
{
    __shared__ float sh1[8], sh2[8], shb[2];
    size_t row = blockIdx.x;
    const float* x = in + row * D;
    int tid = threadIdx.x, lane = tid & 31, wp = tid >> 5;

    float4 v = *reinterpret_cast<const float4*>(x + tid * 4);
    float s = v.x + v.y + v.z + v.w;
    float q = v.x * v.x + v.y * v.y + v.z * v.z + v.w * v.w;
    #pragma unroll
    for (int o = 16; o; o >>= 1) { s += __shfl_down_sync(~0u, s, o); q += __shfl_down_sync(~0u, q, o); }
    if (!lane) { sh1[wp] = s; sh2[wp] = q; }
    __syncthreads();
    if (tid < 32) {
        s = (tid < 8) ? sh1[tid] : 0.f;
        q = (tid < 8) ? sh2[tid] : 0.f;
        #pragma unroll
        for (int o = 4; o; o >>= 1) { s += __shfl_down_sync(~0u, s, o); q += __shfl_down_sync(~0u, q, o); }
        if (!tid) {
            float mu = s * (1.f / D);
            shb[0] = mu;
            shb[1] = rsqrtf(q * (1.f / D) - mu * mu + 1e-5f);
        }
    }
    __syncthreads();
    float mu = shb[0], rs = shb[1];
    float4 wv = *reinterpret_cast<const float4*>(w  + tid * 4);
    float4 bv = *reinterpret_cast<const float4*>(bb + tid * 4);
    float4 o4;
    o4.x = (v.x - mu) * rs * wv.x + bv.x;
    o4.y = (v.y - mu) * rs * wv.y + bv.y;
    o4.z = (v.z - mu) * rs * wv.z + bv.z;
    o4.w = (v.w - mu) * rs * wv.w + bv.w;
    *reinterpret_cast<float4*>(out + row * D + tid * 4) = o4;
}

// ---------------- launch ----------------
extern "C" void kernel_launch(void* const* d_in, const int* in_sizes, int n_in,
                              void* d_out, int out_size)
{
    const float* src  = (const float*)d_in[0];
    const float* mask = (const float*)d_in[1];
    const float* Wq   = (const float*)d_in[2];
    const float* bq   = (const float*)d_in[3];
    const float* Wk   = (const float*)d_in[4];
    const float* bk   = (const float*)d_in[5];
    const float* Wv   = (const float*)d_in[6];
    const float* bv   = (const float*)d_in[7];
    const float* Wo   = (const float*)d_in[8];
    const float* bo   = (const float*)d_in[9];
    const float* ln1w = (const float*)d_in[10];
    const float* ln1b = (const float*)d_in[11];
    const float* W1   = (const float*)d_in[12];
    const float* b1   = (const float*)d_in[13];
    const float* W2   = (const float*)d_in[14];
    const float* b2   = (const float*)d_in[15];
    const float* ln2w = (const float*)d_in[16];
    const float* ln2b = (const float*)d_in[17];
    float* out = (float*)d_out;

    float *pWqkv, *pbqkv, *pQKV, *pP, *pCTX, *pY, *pX, *pHf, *pZ;
    __nv_bfloat16 *pqh, *pql, *poh, *pol, *p1h, *p1l, *p2h, *p2l;
    cudaGetSymbolAddress((void**)&pWqkv, g_Wqkv);
    cudaGetSymbolAddress((void**)&pbqkv, g_bqkv);
    cudaGetSymbolAddress((void**)&pQKV,  g_QKV);
    cudaGetSymbolAddress((void**)&pP,    g_P);
    cudaGetSymbolAddress((void**)&pCTX,  g_CTX);
    cudaGetSymbolAddress((void**)&pY,    g_Y);
    cudaGetSymbolAddress((void**)&pX,    g_X);
    cudaGetSymbolAddress((void**)&pHf,   g_Hf);
    cudaGetSymbolAddress((void**)&pZ,    g_Z);
    cudaGetSymbolAddress((void**)&pqh,   g_qkv_h);
    cudaGetSymbolAddress((void**)&pql,   g_qkv_l);
    cudaGetSymbolAddress((void**)&poh,   g_wo_h);
    cudaGetSymbolAddress((void**)&pol,   g_wo_l);
    cudaGetSymbolAddress((void**)&p1h,   g_w1_h);
    cudaGetSymbolAddress((void**)&p1l,   g_w1_l);
    cudaGetSymbolAddress((void**)&p2h,   g_w2_h);
    cudaGetSymbolAddress((void**)&p2l,   g_w2_l);

    cudaFuncSetAttribute(gemm_mma, cudaFuncAttributeMaxDynamicSharedMemorySize, GEMM_DSMEM);

    // 1) fp32 QKV weight concat + bias
    prep_k<<<(H * D * DK + 255) / 256, 256>>>(Wq, Wk, Wv, bq, bk, bv);

    // 2) weight transpose + bf16 hi/lo split
    convW_k<<<dim3(N3 / 32, D / 32), 256>>>(pWqkv, pqh, pql, D, N3);
    convW_k<<<dim3(D / 32, D / 32),  256>>>(Wo,    poh, pol, D, D);
    convW_k<<<dim3(F / 32, D / 32),  256>>>(W1,    p1h, p1l, D, F);
    convW_k<<<dim3(D / 32, F / 32),  256>>>(W2,    p2h, p2l, F, D);

    // 3) QKV = src @ Wqkv + bqkv
    gemm_mma<<<dim3(N3 / 128, M / 128), 256, GEMM_DSMEM>>>(src, pqh, pql, pQKV, pbqkv, nullptr, N3, D, 0);

    // 4) attention
    attn_logits_k<<<dim3(S / 64, S / 64, B * H), 256>>>(pQKV, mask, pP);
    softmax_k<<<B * H * S, 256>>>(pP);
    attn_ctx_k<<<dim3(1, S / 64, B * H), 256>>>(pP, pQKV, pCTX);

    // 5) Y = src + CTX @ Wo + bo
    gemm_mma<<<dim3(D / 128, M / 128), 256, GEMM_DSMEM>>>(pCTX, poh, pol, pY, bo, src, D, D, 0);

    // 6) X = LN1(Y)
    layernorm_k<<<M, 256>>>(pY, ln1w, ln1b, pX);

    // 7) Hf = relu(X @ W1 + b1)
    gemm_mma<<<dim3(F / 128, M / 128), 256, GEMM_DSMEM>>>(pX, p1h, p1l, pHf, b1, nullptr, F, D, 1);

    // 8) Z = X + Hf @ W2 + b2
    gemm_mma<<<dim3(D / 128, M / 128), 256, GEMM_DSMEM>>>(pHf, p2h, p2l, pZ, b2, pX, D, F, 0);

    // 9) out = LN2(Z)
    layernorm_k<<<M, 256>>>(pZ, ln2w, ln2b, out);
}

// round 4
// speedup vs baseline: 2.5478x; 1.3993x over previous
#include <cuda_runtime.h>
#include <cuda_bf16.h>
#include <math_constants.h>
#include <cstdint>

// ---------------- problem constants ----------------
constexpr int B  = 8;
constexpr int S  = 1024;
constexpr int D  = 1024;
constexpr int H  = 16;
constexpr int DK = 64;
constexpr int F  = 4096;
constexpr int M  = B * S;        // 8192 rows
constexpr int N3 = 3 * D;        // 3072 (Q|K|V concat)

// ---------------- scratch (static device memory; no allocation) ----------------
__device__ __align__(128) float g_Wqkv[(size_t)D * N3];
__device__ __align__(128) float g_bqkv[N3];
__device__ __align__(128) float g_QKV [(size_t)M * N3];
__device__ __align__(128) float g_CTX [(size_t)M * D];
__device__ __align__(128) float g_Y   [(size_t)M * D];
__device__ __align__(128) float g_X   [(size_t)M * D];
__device__ __align__(128) float g_Hf  [(size_t)M * F];
__device__ __align__(128) float g_Z   [(size_t)M * D];

// packed bf16 hi/lo weight planes, K-major: plane[n*K + k]
__device__ __align__(128) __nv_bfloat16 g_qkv_h[(size_t)N3 * D];
__device__ __align__(128) __nv_bfloat16 g_qkv_l[(size_t)N3 * D];
__device__ __align__(128) __nv_bfloat16 g_wo_h [(size_t)D * D];
__device__ __align__(128) __nv_bfloat16 g_wo_l [(size_t)D * D];
__device__ __align__(128) __nv_bfloat16 g_w1_h [(size_t)F * D];
__device__ __align__(128) __nv_bfloat16 g_w1_l [(size_t)F * D];
__device__ __align__(128) __nv_bfloat16 g_w2_h [(size_t)D * F];
__device__ __align__(128) __nv_bfloat16 g_w2_l [(size_t)D * F];

// ---------------- PTX helpers ----------------
__device__ __forceinline__ uint32_t smem_u32(const void* p) {
    uint32_t a;
    asm("{ .reg .u64 t; cvta.to.shared.u64 t, %1; cvt.u32.u64 %0, t; }" : "=r"(a) : "l"(p));
    return a;
}
__device__ __forceinline__ void sts64(uint32_t a, uint32_t x, uint32_t y) {
    asm volatile("st.shared.v2.b32 [%0], {%1, %2};" :: "r"(a), "r"(x), "r"(y));
}
#define CP16(dst, src) \
    asm volatile("cp.async.cg.shared.global [%0], [%1], 16;" :: "r"(dst), "l"(src) : "memory")
#define CP_COMMIT() asm volatile("cp.async.commit_group;" ::: "memory")
#define CP_WAIT0()  asm volatile("cp.async.wait_group 0;" ::: "memory")

#define LDSM4(r, addr) \
    asm volatile("ldmatrix.sync.aligned.m8n8.x4.shared.b16 {%0, %1, %2, %3}, [%4];" \
        : "=r"((r)[0]), "=r"((r)[1]), "=r"((r)[2]), "=r"((r)[3]) : "r"(addr))
#define LDSM4T(r, addr) \
    asm volatile("ldmatrix.sync.aligned.m8n8.x4.trans.shared.b16 {%0, %1, %2, %3}, [%4];" \
        : "=r"((r)[0]), "=r"((r)[1]), "=r"((r)[2]), "=r"((r)[3]) : "r"(addr))

#define MMA16816(d, a, b) \
    asm volatile("mma.sync.aligned.m16n8k16.row.col.f32.bf16.bf16.f32 " \
        "{%0, %1, %2, %3}, {%4, %5, %6, %7}, {%8, %9}, {%0, %1, %2, %3};" \
        : "+f"((d)[0]), "+f"((d)[1]), "+f"((d)[2]), "+f"((d)[3]) \
        : "r"((a)[0]), "r"((a)[1]), "r"((a)[2]), "r"((a)[3]), "r"((b)[0]), "r"((b)[1]))

__device__ __forceinline__ uint32_t pack_hi(float x, float y) {
    __nv_bfloat162 h; h.x = __float2bfloat16(x); h.y = __float2bfloat16(y);
    return *reinterpret_cast<uint32_t*>(&h);
}
__device__ __forceinline__ uint32_t pack_lo(float x, float y, uint32_t hi) {
    __nv_bfloat162 h = *reinterpret_cast<__nv_bfloat162*>(&hi);
    __nv_bfloat162 l;
    l.x = __float2bfloat16(x - __bfloat162float(h.x));
    l.y = __float2bfloat16(y - __bfloat162float(h.y));
    return *reinterpret_cast<uint32_t*>(&l);
}

// ---------------- weight repack (fp32 QKV concat) ----------------
__global__ __launch_bounds__(256) void prep_k(
    const float* __restrict__ Wq, const float* __restrict__ Wk, const float* __restrict__ Wv,
    const float* __restrict__ bq, const float* __restrict__ bk, const float* __restrict__ bv)
{
    int idx = blockIdx.x * blockDim.x + threadIdx.x;
    int total = H * D * DK;
    if (idx < total) {
        int h   = idx / (D * DK);
        int rem = idx - h * (D * DK);
        int d   = rem / DK;
        int k   = rem - d * DK;
        size_t dst = (size_t)d * N3 + h * DK + k;
        g_Wqkv[dst        ] = Wq[idx];
        g_Wqkv[dst + D    ] = Wk[idx];
        g_Wqkv[dst + 2 * D] = Wv[idx];
    }
    if (idx < D) {
        g_bqkv[idx        ] = bq[idx];
        g_bqkv[idx + D    ] = bk[idx];
        g_bqkv[idx + 2 * D] = bv[idx];
    }
}

// ---------------- transpose + bf16 hi/lo split: W[K][N] -> planes [N][K] ----------------
__global__ __launch_bounds__(256) void convW_k(
    const float* __restrict__ W, __nv_bfloat16* __restrict__ oh,
    __nv_bfloat16* __restrict__ ol, int Kk, int Nn)
{
    __shared__ float t[32][33];
    int n0 = blockIdx.x * 32, k0 = blockIdx.y * 32;
    int tx = threadIdx.x & 31, ty = threadIdx.x >> 5;
    #pragma unroll
    for (int i = 0; i < 4; i++)
        t[ty + i * 8][tx] = W[(size_t)(k0 + ty + i * 8) * Nn + n0 + tx];
    __syncthreads();
    #pragma unroll
    for (int i = 0; i < 4; i++) {
        int n = n0 + ty + i * 8;
        float v = t[tx][ty + i * 8];
        __nv_bfloat16 hv = __float2bfloat16(v);
        oh[(size_t)n * Kk + k0 + tx] = hv;
        ol[(size_t)n * Kk + k0 + tx] = __float2bfloat16(v - __bfloat162float(hv));
    }
}

// ---------------- HMMA GEMM (unchanged from R3) ----------------
constexpr int GLDS  = 40;
constexpr int GPL   = 128 * GLDS * 2;     // 10240
constexpr int GSTG  = 4 * GPL;            // 40960
constexpr int GEMM_DSMEM = 2 * GSTG;      // 81920

__global__ __launch_bounds__(256, 1) void gemm_mma(
    const float* __restrict__ A, const __nv_bfloat16* __restrict__ Bhp,
    const __nv_bfloat16* __restrict__ Blp, float* __restrict__ C,
    const float* __restrict__ bias, const float* __restrict__ resid,
    int Nn, int Kk, int relu)
{
    extern __shared__ char smraw[];
    const uint32_t sbase = smem_u32(smraw);
    const int tid  = threadIdx.x;
    const int lane = tid & 31;
    const int wid  = tid >> 5;
    const int wm   = wid & 1;
    const int wn   = wid >> 1;
    const int m0 = blockIdx.y * 128;
    const int n0 = blockIdx.x * 128;
    const int nk = Kk >> 5;

    float acc[4][4][4];
    #pragma unroll
    for (int i = 0; i < 4; i++)
        #pragma unroll
        for (int j = 0; j < 4; j++)
            #pragma unroll
            for (int q = 0; q < 4; q++) acc[i][j][q] = 0.f;

    float4 aReg[4];

    auto ldgA = [&](int ci) {
        #pragma unroll
        for (int p = 0; p < 4; p++) {
            int f = tid + (p << 8);
            int r = f >> 3, sg = f & 7;
            aReg[p] = *reinterpret_cast<const float4*>(
                A + (size_t)(m0 + r) * Kk + (ci << 5) + sg * 4);
        }
    };
    auto stsA = [&](int stage) {
        const uint32_t ab = sbase + stage * GSTG;
        #pragma unroll
        for (int p = 0; p < 4; p++) {
            int f = tid + (p << 8);
            int r = f >> 3, sg = f & 7;
            float4 v = aReg[p];
            uint32_t h01 = pack_hi(v.x, v.y), h23 = pack_hi(v.z, v.w);
            uint32_t l01 = pack_lo(v.x, v.y, h01), l23 = pack_lo(v.z, v.w, h23);
            uint32_t off = (uint32_t)(r * (GLDS * 2) + sg * 8);
            sts64(ab + off,       h01, h23);
            sts64(ab + GPL + off, l01, l23);
        }
    };
    auto cpB = [&](int ci, int stage) {
        const uint32_t bb = sbase + stage * GSTG + 2 * GPL;
        #pragma unroll
        for (int p = 0; p < 2; p++) {
            int f = tid + (p << 8);
            int r = f >> 2, c = f & 3;
            uint32_t dst = bb + (uint32_t)(r * (GLDS * 2) + c * 16);
            const __nv_bfloat16* sh = Bhp + (size_t)(n0 + r) * Kk + (ci << 5) + c * 8;
            const __nv_bfloat16* sl = Blp + (size_t)(n0 + r) * Kk + (ci << 5) + c * 8;
            CP16(dst,       sh);
            CP16(dst + GPL, sl);
        }
        CP_COMMIT();
    };
    auto compute = [&](int stage) {
        const uint32_t ab = sbase + stage * GSTG;
        const uint32_t bb = ab + 2 * GPL;
        #pragma unroll
        for (int h = 0; h < 2; h++) {
            uint32_t Ahf[4][4], Alf[4][4], Bhf[4][2], Blf[4][2];
            #pragma unroll
            for (int i = 0; i < 4; i++) {
                int r = wm * 64 + i * 16 + (lane & 15);
                uint32_t ad = ab + (uint32_t)(r * (GLDS * 2) + h * 32 + (lane >> 4) * 16);
                LDSM4(Ahf[i], ad);
                LDSM4(Alf[i], ad + GPL);
            }
            #pragma unroll
            for (int jj = 0; jj < 2; jj++) {
                int nb = wn * 32 + jj * 16;
                int l8 = lane & 7, mt = lane >> 3;
                int nr = nb + (mt >> 1) * 8 + l8;
                uint32_t bd = bb + (uint32_t)(nr * (GLDS * 2) + h * 32 + (mt & 1) * 16);
                uint32_t q[4];
                LDSM4(q, bd);
                Bhf[jj * 2][0] = q[0]; Bhf[jj * 2][1] = q[1];
                Bhf[jj * 2 + 1][0] = q[2]; Bhf[jj * 2 + 1][1] = q[3];
                LDSM4(q, bd + GPL);
                Blf[jj * 2][0] = q[0]; Blf[jj * 2][1] = q[1];
                Blf[jj * 2 + 1][0] = q[2]; Blf[jj * 2 + 1][1] = q[3];
            }
            #pragma unroll
            for (int i = 0; i < 4; i++)
                #pragma unroll
                for (int j = 0; j < 4; j++) {
                    MMA16816(acc[i][j], Ahf[i], Bhf[j]);
                    MMA16816(acc[i][j], Alf[i], Bhf[j]);
                    MMA16816(acc[i][j], Ahf[i], Blf[j]);
                }
        }
    };

    ldgA(0);
    cpB(0, 0);
    stsA(0);
    CP_WAIT0();
    __syncthreads();

    for (int i = 0; i < nk; i++) {
        const int st = i & 1;
        if (i + 1 < nk) { ldgA(i + 1); cpB(i + 1, st ^ 1); }
        compute(st);
        if (i + 1 < nk) stsA(st ^ 1);
        CP_WAIT0();
        __syncthreads();
    }

    #pragma unroll
    for (int i = 0; i < 4; i++) {
        int r = m0 + wm * 64 + i * 16 + (lane >> 2);
        #pragma unroll
        for (int j = 0; j < 4; j++) {
            int c = n0 + wn * 32 + j * 8 + (lane & 3) * 2;
            float2 v0 = { acc[i][j][0], acc[i][j][1] };
            float2 v1 = { acc[i][j][2], acc[i][j][3] };
            float2 bv = *reinterpret_cast<const float2*>(bias + c);
            v0.x += bv.x; v0.y += bv.y;
            v1.x += bv.x; v1.y += bv.y;
            if (resid) {
                float2 r0 = *reinterpret_cast<const float2*>(resid + (size_t)r * Nn + c);
                float2 r1 = *reinterpret_cast<const float2*>(resid + (size_t)(r + 8) * Nn + c);
                v0.x += r0.x; v0.y += r0.y;
                v1.x += r1.x; v1.y += r1.y;
            }
            if (relu) {
                v0.x = fmaxf(v0.x, 0.f); v0.y = fmaxf(v0.y, 0.f);
                v1.x = fmaxf(v1.x, 0.f); v1.y = fmaxf(v1.y, 0.f);
            }
            *reinterpret_cast<float2*>(C + (size_t)r * Nn + c) = v0;
            *reinterpret_cast<float2*>(C + (size_t)(r + 8) * Nn + c) = v1;
        }
    }
}

// ---------------- fused flash attention ----------------
// Grid (S/128, B*H). CTA: 128 q-rows, 8 warps x 16 rows. DK=64.
// QK^T and P.V on bf16 mma with hi/lo 3-term split; online softmax in registers.
// Smem: Q hi/lo + double-buffered K hi/lo + V hi/lo, 72-half padded rows.
constexpr int FR  = 72;               // halves per smem row (64 data + 8 pad)
constexpr int FRB = FR * 2;           // 144 bytes
constexpr int FPL = 128 * FRB;        // plane bytes = 18432
constexpr int FST = 2 * FPL;          // hi+lo = 36864
constexpr int FA_DSMEM = 5 * FST;     // Q + 2*K + 2*V = 184320

__global__ __launch_bounds__(256, 1) void flash_attn(
    const float* __restrict__ QKV, const float* __restrict__ mask, float* __restrict__ CTX)
{
    extern __shared__ char smraw[];
    const uint32_t sb = smem_u32(smraw);
    const int tid  = threadIdx.x;
    const int lane = tid & 31;
    const int wid  = tid >> 5;
    const int bh = blockIdx.y;
    const int b  = bh >> 4, h = bh & 15;
    const int s0 = blockIdx.x * 128;

    const float* Qg = QKV + (size_t)(b * S + s0) * N3 + h * DK;
    const float* Kg = QKV + (size_t)b * S * N3 + D + h * DK;
    const float* Vg = Kg + D;

    const uint32_t qb = sb;

    // ---- load Q tile (128 x 64 fp32 -> hi/lo bf16) ----
    #pragma unroll
    for (int p = 0; p < 8; p++) {
        int f = tid + (p << 8);
        int r = f >> 4, c = (f & 15) << 2;
        float4 v = *reinterpret_cast<const float4*>(Qg + (size_t)r * N3 + c);
        uint32_t h01 = pack_hi(v.x, v.y), h23 = pack_hi(v.z, v.w);
        uint32_t l01 = pack_lo(v.x, v.y, h01), l23 = pack_lo(v.z, v.w, h23);
        uint32_t off = (uint32_t)(r * FRB + c * 2);
        sts64(qb + off,       h01, h23);
        sts64(qb + FPL + off, l01, l23);
    }

    float4 stg[8];
    auto ldgT = [&](const float* base, int t) {
        #pragma unroll
        for (int p = 0; p < 8; p++) {
            int f = tid + (p << 8);
            int r = f >> 4, c = (f & 15) << 2;
            stg[p] = *reinterpret_cast<const float4*>(base + (size_t)(t * 128 + r) * N3 + c);
        }
    };
    auto stsT = [&](uint32_t dst) {
        #pragma unroll
        for (int p = 0; p < 8; p++) {
            int f = tid + (p << 8);
            int r = f >> 4, c = (f & 15) << 2;
            float4 v = stg[p];
            uint32_t h01 = pack_hi(v.x, v.y), h23 = pack_hi(v.z, v.w);
            uint32_t l01 = pack_lo(v.x, v.y, h01), l23 = pack_lo(v.z, v.w, h23);
            uint32_t off = (uint32_t)(r * FRB + c * 2);
            sts64(dst + off,       h01, h23);
            sts64(dst + FPL + off, l01, l23);
        }
    };
    auto kstage = [&](int st) { return sb + (1 + st) * FST; };
    auto vstage = [&](int st) { return sb + (3 + st) * FST; };

    ldgT(Kg, 0); stsT(kstage(0));
    ldgT(Vg, 0); stsT(vstage(0));
    __syncthreads();

    // ---- per-thread softmax state ----
    float mrow0 = -1e30f, mrow1 = -1e30f;
    float l0 = 0.f, l1 = 0.f;
    float O[8][4];
    #pragma unroll
    for (int nj = 0; nj < 8; nj++)
        #pragma unroll
        for (int q = 0; q < 4; q++) O[nj][q] = 0.f;

    const int r0 = wid * 16 + (lane >> 2);          // CTA-local row
    const int l8 = lane & 7, mt = lane >> 3;

    constexpr int NT = S / 128;                      // 8 tiles
    for (int t = 0; t < NT; t++) {
        const int st = t & 1;
        const uint32_t kst = kstage(st), vst = vstage(st);

        if (t + 1 < NT) ldgT(Kg, t + 1);             // in flight under S-MMA

        // ---- S = Q K^T (16x128 per warp), 3-term hi/lo ----
        float Sr[16][4];
        #pragma unroll
        for (int j = 0; j < 16; j++)
            #pragma unroll
            for (int q = 0; q < 4; q++) Sr[j][q] = 0.f;

        #pragma unroll
        for (int c = 0; c < 4; c++) {
            uint32_t Ah[4], Al[4];
            uint32_t ad = qb + (uint32_t)((wid * 16 + (lane & 15)) * FRB + c * 32 + (lane >> 4) * 16);
            LDSM4(Ah, ad);
            LDSM4(Al, ad + FPL);
            #pragma unroll
            for (int jj = 0; jj < 8; jj++) {
                uint32_t bd = kst + (uint32_t)((jj * 16 + (mt >> 1) * 8 + l8) * FRB + c * 32 + (mt & 1) * 16);
                uint32_t bh4[4], bl4[4];
                LDSM4(bh4, bd);
                LDSM4(bl4, bd + FPL);
                MMA16816(Sr[jj * 2],     Ah, bh4);
                MMA16816(Sr[jj * 2],     Al, bh4);
                MMA16816(Sr[jj * 2],     Ah, bl4);
                MMA16816(Sr[jj * 2 + 1], Ah, bh4 + 2);
                MMA16816(Sr[jj * 2 + 1], Al, bh4 + 2);
                MMA16816(Sr[jj * 2 + 1], Ah, bl4 + 2);
            }
        }

        if (t + 1 < NT) { stsT(kstage(st ^ 1)); ldgT(Vg, t + 1); }

        // ---- scale + mask ----
        const float* mr0 = mask + (size_t)(s0 + r0) * S + t * 128;
        const float* mr1 = mr0 + 8 * S;
        #pragma unroll
        for (int j = 0; j < 16; j++) {
            int tc = j * 8 + (lane & 3) * 2;
            float2 m0 = *reinterpret_cast<const float2*>(mr0 + tc);
            float2 m1 = *reinterpret_cast<const float2*>(mr1 + tc);
            Sr[j][0] = Sr[j][0] * 0.125f - 1e9f * m0.x;
            Sr[j][1] = Sr[j][1] * 0.125f - 1e9f * m0.y;
            Sr[j][2] = Sr[j][2] * 0.125f - 1e9f * m1.x;
            Sr[j][3] = Sr[j][3] * 0.125f - 1e9f * m1.y;
        }

        // ---- online softmax ----
        float mt0 = -1e30f, mt1 = -1e30f;
        #pragma unroll
        for (int j = 0; j < 16; j++) {
            mt0 = fmaxf(mt0, fmaxf(Sr[j][0], Sr[j][1]));
            mt1 = fmaxf(mt1, fmaxf(Sr[j][2], Sr[j][3]));
        }
        mt0 = fmaxf(mt0, __shfl_xor_sync(~0u, mt0, 1));
        mt0 = fmaxf(mt0, __shfl_xor_sync(~0u, mt0, 2));
        mt1 = fmaxf(mt1, __shfl_xor_sync(~0u, mt1, 1));
        mt1 = fmaxf(mt1, __shfl_xor_sync(~0u, mt1, 2));
        float mn0 = fmaxf(mrow0, mt0), mn1 = fmaxf(mrow1, mt1);
        float a0 = __expf(mrow0 - mn0), a1 = __expf(mrow1 - mn1);
        mrow0 = mn0; mrow1 = mn1;
        #pragma unroll
        for (int nj = 0; nj < 8; nj++) {
            O[nj][0] *= a0; O[nj][1] *= a0;
            O[nj][2] *= a1; O[nj][3] *= a1;
        }
        float rs0 = 0.f, rs1 = 0.f;
        #pragma unroll
        for (int j = 0; j < 16; j++) {
            Sr[j][0] = __expf(Sr[j][0] - mn0);
            Sr[j][1] = __expf(Sr[j][1] - mn0);
            Sr[j][2] = __expf(Sr[j][2] - mn1);
            Sr[j][3] = __expf(Sr[j][3] - mn1);
            rs0 += Sr[j][0] + Sr[j][1];
            rs1 += Sr[j][2] + Sr[j][3];
        }
        rs0 += __shfl_xor_sync(~0u, rs0, 1);
        rs0 += __shfl_xor_sync(~0u, rs0, 2);
        rs1 += __shfl_xor_sync(~0u, rs1, 1);
        rs1 += __shfl_xor_sync(~0u, rs1, 2);
        l0 = l0 * a0 + rs0;
        l1 = l1 * a1 + rs1;

        // ---- O += P V, P hi/lo from registers, V via trans-ldmatrix ----
        #pragma unroll
        for (int c = 0; c < 8; c++) {
            uint32_t Ph[4], Pl[4];
            Ph[0] = pack_hi(Sr[2 * c][0], Sr[2 * c][1]);
            Pl[0] = pack_lo(Sr[2 * c][0], Sr[2 * c][1], Ph[0]);
            Ph[1] = pack_hi(Sr[2 * c][2], Sr[2 * c][3]);
            Pl[1] = pack_lo(Sr[2 * c][2], Sr[2 * c][3], Ph[1]);
            Ph[2] = pack_hi(Sr[2 * c + 1][0], Sr[2 * c + 1][1]);
            Pl[2] = pack_lo(Sr[2 * c + 1][0], Sr[2 * c + 1][1], Ph[2]);
            Ph[3] = pack_hi(Sr[2 * c + 1][2], Sr[2 * c + 1][3]);
            Pl[3] = pack_lo(Sr[2 * c + 1][2], Sr[2 * c + 1][3], Ph[3]);
            #pragma unroll
            for (int njp = 0; njp < 4; njp++) {
                uint32_t bd = vst + (uint32_t)((c * 16 + ((lane >> 3) & 1) * 8 + l8) * FRB
                                               + (njp * 16 + (lane >> 4) * 8) * 2);
                uint32_t vh4[4], vl4[4];
                LDSM4T(vh4, bd);
                LDSM4T(vl4, bd + FPL);
                MMA16816(O[njp * 2],     Ph, vh4);
                MMA16816(O[njp * 2],     Pl, vh4);
                MMA16816(O[njp * 2],     Ph, vl4);
                MMA16816(O[njp * 2 + 1], Ph, vh4 + 2);
                MMA16816(O[njp * 2 + 1], Pl, vh4 + 2);
                MMA16816(O[njp * 2 + 1], Ph, vl4 + 2);
            }
        }

        if (t + 1 < NT) stsT(vstage(st ^ 1));
        __syncthreads();
    }

    // ---- write CTX ----
    const float il0 = 1.f / l0, il1 = 1.f / l1;
    const int sg0 = b * S + s0 + r0;
    #pragma unroll
    for (int nj = 0; nj < 8; nj++) {
        int c = h * DK + nj * 8 + (lane & 3) * 2;
        float2 v0 = { O[nj][0] * il0, O[nj][1] * il0 };
        float2 v1 = { O[nj][2] * il1, O[nj][3] * il1 };
        *reinterpret_cast<float2*>(CTX + (size_t)sg0 * D + c) = v0;
        *reinterpret_cast<float2*>(CTX + (size_t)(sg0 + 8) * D + c) = v1;
    }
}

// ---------------- LayerNorm over last dim (1024) ----------------
__global__ __launch_bounds__(256) void layernorm_k(
    const float* __restrict__ in, const float* __restrict__ w,
    const float* __restrict__ bb, float* __restrict__ out)
{
    __shared__ float sh1[8], sh2[8], shb[2];
    size_t row = blockIdx.x;
    const float* x = in + row * D;
    int tid = threadIdx.x, lane = tid & 31, wp = tid >> 5;

    float4 v = *reinterpret_cast<const float4*>(x + tid * 4);
    float s = v.x + v.y + v.z + v.w;
    float q = v.x * v.x + v.y * v.y + v.z * v.z + v.w * v.w;
    #pragma unroll
    for (int o = 16; o; o >>= 1) { s += __shfl_down_sync(~0u, s, o); q += __shfl_down_sync(~0u, q, o); }
    if (!lane) { sh1[wp] = s; sh2[wp] = q; }
    __syncthreads();
    if (tid < 32) {
        s = (tid < 8) ? sh1[tid] : 0.f;
        q = (tid < 8) ? sh2[tid] : 0.f;
        #pragma unroll
        for (int o = 4; o; o >>= 1) { s += __shfl_down_sync(~0u, s, o); q += __shfl_down_sync(~0u, q, o); }
        if (!tid) {
            float mu = s * (1.f / D);
            shb[0] = mu;
            shb[1] = rsqrtf(q * (1.f / D) - mu * mu + 1e-5f);
        }
    }
    __syncthreads();
    float mu = shb[0], rs = shb[1];
    float4 wv = *reinterpret_cast<const float4*>(w  + tid * 4);
    float4 bv = *reinterpret_cast<const float4*>(bb + tid * 4);
    float4 o4;
    o4.x = (v.x - mu) * rs * wv.x + bv.x;
    o4.y = (v.y - mu) * rs * wv.y + bv.y;
    o4.z = (v.z - mu) * rs * wv.z + bv.z;
    o4.w = (v.w - mu) * rs * wv.w + bv.w;
    *reinterpret_cast<float4*>(out + row * D + tid * 4) = o4;
}

// ---------------- launch ----------------
extern "C" void kernel_launch(void* const* d_in, const int* in_sizes, int n_in,
                              void* d_out, int out_size)
{
    const float* src  = (const float*)d_in[0];
    const float* mask = (const float*)d_in[1];
    const float* Wq   = (const float*)d_in[2];
    const float* bq   = (const float*)d_in[3];
    const float* Wk   = (const float*)d_in[4];
    const float* bk   = (const float*)d_in[5];
    const float* Wv   = (const float*)d_in[6];
    const float* bv   = (const float*)d_in[7];
    const float* Wo   = (const float*)d_in[8];
    const float* bo   = (const float*)d_in[9];
    const float* ln1w = (const float*)d_in[10];
    const float* ln1b = (const float*)d_in[11];
    const float* W1   = (const float*)d_in[12];
    const float* b1   = (const float*)d_in[13];
    const float* W2   = (const float*)d_in[14];
    const float* b2   = (const float*)d_in[15];
    const float* ln2w = (const float*)d_in[16];
    const float* ln2b = (const float*)d_in[17];
    float* out = (float*)d_out;

    float *pWqkv, *pbqkv, *pQKV, *pCTX, *pY, *pX, *pHf, *pZ;
    __nv_bfloat16 *pqh, *pql, *poh, *pol, *p1h, *p1l, *p2h, *p2l;
    cudaGetSymbolAddress((void**)&pWqkv, g_Wqkv);
    cudaGetSymbolAddress((void**)&pbqkv, g_bqkv);
    cudaGetSymbolAddress((void**)&pQKV,  g_QKV);
    cudaGetSymbolAddress((void**)&pCTX,  g_CTX);
    cudaGetSymbolAddress((void**)&pY,    g_Y);
    cudaGetSymbolAddress((void**)&pX,    g_X);
    cudaGetSymbolAddress((void**)&pHf,   g_Hf);
    cudaGetSymbolAddress((void**)&pZ,    g_Z);
    cudaGetSymbolAddress((void**)&pqh,   g_qkv_h);
    cudaGetSymbolAddress((void**)&pql,   g_qkv_l);
    cudaGetSymbolAddress((void**)&poh,   g_wo_h);
    cudaGetSymbolAddress((void**)&pol,   g_wo_l);
    cudaGetSymbolAddress((void**)&p1h,   g_w1_h);
    cudaGetSymbolAddress((void**)&p1l,   g_w1_l);
    cudaGetSymbolAddress((void**)&p2h,   g_w2_h);
    cudaGetSymbolAddress((void**)&p2l,   g_w2_l);

    cudaFuncSetAttribute(gemm_mma,   cudaFuncAttributeMaxDynamicSharedMemorySize, GEMM_DSMEM);
    cudaFuncSetAttribute(flash_attn, cudaFuncAttributeMaxDynamicSharedMemorySize, FA_DSMEM);

    // 1) fp32 QKV weight concat + bias
    prep_k<<<(H * D * DK + 255) / 256, 256>>>(Wq, Wk, Wv, bq, bk, bv);

    // 2) weight transpose + bf16 hi/lo split
    convW_k<<<dim3(N3 / 32, D / 32), 256>>>(pWqkv, pqh, pql, D, N3);
    convW_k<<<dim3(D / 32, D / 32),  256>>>(Wo,    poh, pol, D, D);
    convW_k<<<dim3(F / 32, D / 32),  256>>>(W1,    p1h, p1l, D, F);
    convW_k<<<dim3(D / 32, F / 32),  256>>>(W2,    p2h, p2l, F, D);

    // 3) QKV = src @ Wqkv + bqkv
    gemm_mma<<<dim3(N3 / 128, M / 128), 256, GEMM_DSMEM>>>(src, pqh, pql, pQKV, pbqkv, nullptr, N3, D, 0);

    // 4) fused attention -> CTX (head-concat layout)
    flash_attn<<<dim3(S / 128, B * H), 256, FA_DSMEM>>>(pQKV, mask, pCTX);

    // 5) Y = src + CTX @ Wo + bo
    gemm_mma<<<dim3(D / 128, M / 128), 256, GEMM_DSMEM>>>(pCTX, poh, pol, pY, bo, src, D, D, 0);

    // 6) X = LN1(Y)
    layernorm_k<<<M, 256>>>(pY, ln1w, ln1b, pX);

    // 7) Hf = relu(X @ W1 + b1)
    gemm_mma<<<dim3(F / 128, M / 128), 256, GEMM_DSMEM>>>(pX, p1h, p1l, pHf, b1, nullptr, F, D, 1);

    // 8) Z = X + Hf @ W2 + b2
    gemm_mma<<<dim3(D / 128, M / 128), 256, GEMM_DSMEM>>>(pHf, p2h, p2l, pZ, b2, pX, D, F, 0);

    // 9) out = LN2(Z)
    layernorm_k<<<M, 256>>>(pZ, ln2w, ln2b, out);
}